// round 5
// baseline (speedup 1.0000x reference)
#include <cuda_runtime.h>
#include <cuda_bf16.h>
#include <math.h>
#include <stdint.h>

// ---------------------------------------------------------------------------
// Problem constants
// ---------------------------------------------------------------------------
#define BB    2
#define SSEQ  1024
#define DDIM  1024
#define HHH   16
#define DKV   64
#define DHH   4096
#define LLAY  8
#define VVOC  256
#define MM    (BB*SSEQ)        // 2048
#define NQKV  3072

// ---------------------------------------------------------------------------
// Scratch (device globals: allocation-free)
// ---------------------------------------------------------------------------
__device__ float g_x  [MM*DDIM];
__device__ float g_h  [MM*DDIM];
__device__ float g_qkv[MM*NQKV];

__device__ __nv_bfloat16 g_xhi[MM*DDIM], g_xlo[MM*DDIM];
__device__ __nv_bfloat16 g_ohi[MM*DDIM], g_olo[MM*DDIM];
__device__ __nv_bfloat16 g_hhi[MM*DDIM], g_hlo[MM*DDIM];
__device__ __nv_bfloat16 g_thi[MM*DHH], g_tlo[MM*DHH];

__device__ __nv_bfloat16 g_Wqkv_hi[LLAY*NQKV*DDIM], g_Wqkv_lo[LLAY*NQKV*DDIM];
__device__ __nv_bfloat16 g_Wo_hi  [LLAY*DDIM*DDIM], g_Wo_lo  [LLAY*DDIM*DDIM];
__device__ __nv_bfloat16 g_W1_hi  [LLAY*DHH*DDIM],  g_W1_lo  [LLAY*DHH*DDIM];
__device__ __nv_bfloat16 g_W2_hi  [LLAY*DDIM*DHH],  g_W2_lo  [LLAY*DDIM*DHH];
__device__ __nv_bfloat16 g_Wr_hi  [VVOC*DDIM],      g_Wr_lo  [VVOC*DDIM];
__device__ float g_bqkv[LLAY*NQKV];

// ---------------------------------------------------------------------------
// Helpers
// ---------------------------------------------------------------------------
__device__ __forceinline__ uint32_t smem_u32(const void* p) {
    uint32_t a;
    asm("{ .reg .u64 t; cvta.to.shared.u64 t, %1; cvt.u32.u64 %0, t; }"
        : "=r"(a) : "l"(p));
    return a;
}

__device__ __forceinline__ void ldmx4(uint32_t* r, uint32_t addr) {
    asm volatile("ldmatrix.sync.aligned.m8n8.x4.shared.b16 {%0,%1,%2,%3}, [%4];"
        : "=r"(r[0]), "=r"(r[1]), "=r"(r[2]), "=r"(r[3]) : "r"(addr));
}

__device__ __forceinline__ void mma16816(float* d, const uint32_t* a,
                                         uint32_t b0, uint32_t b1) {
    asm volatile("mma.sync.aligned.m16n8k16.row.col.f32.bf16.bf16.f32 "
        "{%0,%1,%2,%3}, {%4,%5,%6,%7}, {%8,%9}, {%0,%1,%2,%3};"
        : "+f"(d[0]), "+f"(d[1]), "+f"(d[2]), "+f"(d[3])
        : "r"(a[0]), "r"(a[1]), "r"(a[2]), "r"(a[3]), "r"(b0), "r"(b1));
}

__device__ __forceinline__ void cp16(uint32_t dst, const void* src) {
    asm volatile("cp.async.cg.shared.global [%0], [%1], 16;"
        :: "r"(dst), "l"(src) : "memory");
}
#define CP_COMMIT() asm volatile("cp.async.commit_group;" ::: "memory")

template<int N> __device__ __forceinline__ void cp_wait();
template<> __device__ __forceinline__ void cp_wait<0>() {
    asm volatile("cp.async.wait_group 0;" ::: "memory");
}
template<> __device__ __forceinline__ void cp_wait<1>() {
    asm volatile("cp.async.wait_group 1;" ::: "memory");
}

__device__ __forceinline__ float gelu_exact(float v) {
    return 0.5f * v * (1.0f + erff(v * 0.70710678118654752f));
}

__device__ __forceinline__ void split1(float v, __nv_bfloat16& hi, __nv_bfloat16& lo) {
    hi = __float2bfloat16(v);
    lo = __float2bfloat16(v - __bfloat162float(hi));
}

// ---------------------------------------------------------------------------
// GEMM: C = act(A @ Bt^T + bias) + res ; bf16 hi/lo pre-split operands.
// D = Ahi*Bhi + Ahi*Blo + Alo*Bhi (fp32 accum).
// BM=128, BN in {128,256}, BK=32, 8 warps (2 x 4), cp.async NST stages.
// ---------------------------------------------------------------------------
#define LDB 80

template<int BN, int MINB, int NST>
__global__ void __launch_bounds__(256, MINB)
gemm_pair(const __nv_bfloat16* __restrict__ Ahi, const __nv_bfloat16* __restrict__ Alo,
          const __nv_bfloat16* __restrict__ Bhi, const __nv_bfloat16* __restrict__ Blo,
          const float* __restrict__ bias, const float* __restrict__ res,
          float* __restrict__ Cf,
          __nv_bfloat16* __restrict__ Chi, __nv_bfloat16* __restrict__ Clo,
          int M, int N, int K, int gelu)
{
    constexpr int NH      = BN / 128;            // B 32-row halves per warp
    constexpr int OFF_ALO = 128 * LDB;
    constexpr int OFF_BHI = 256 * LDB;
    constexpr int BLO_REL = BN * LDB;            // Blo offset relative to Bhi
    constexpr int STAGE   = (256 + 2 * BN) * LDB;

    extern __shared__ char sm[];
    const uint32_t smb = smem_u32(sm);

    const int tid  = threadIdx.x;
    const int lane = tid & 31;
    const int wid  = tid >> 5;
    const int wr   = wid >> 2;          // 0..1
    const int wc   = wid & 3;           // 0..3
    const int m0   = blockIdx.y * 128;
    const int n0   = blockIdx.x * BN;

    // staging: thread -> row r (+64*p), 16B chunk ch
    const int r  = tid >> 2;
    const int ch = tid & 3;

    const int nIt = K >> 5;

    auto issue = [&](int it) {
        const uint32_t sp = smb + (uint32_t)((it % NST) * STAGE + r * LDB + ch * 16);
        const size_t koff = (size_t)it * 32 + ch * 8;
#pragma unroll
        for (int p = 0; p < 2; p++) {
            const size_t g = (size_t)(m0 + r + p * 64) * K + koff;
            cp16(sp + p * 64 * LDB,           Ahi + g);
            cp16(sp + OFF_ALO + p * 64 * LDB, Alo + g);
        }
#pragma unroll
        for (int p = 0; p < BN / 64; p++) {
            const size_t g = (size_t)(n0 + r + p * 64) * K + koff;
            cp16(sp + OFF_BHI + p * 64 * LDB,           Bhi + g);
            cp16(sp + OFF_BHI + BLO_REL + p * 64 * LDB, Blo + g);
        }
        CP_COMMIT();
    };

    float acc[4][NH * 4][4];
#pragma unroll
    for (int i = 0; i < 4; i++)
#pragma unroll
        for (int j = 0; j < NH * 4; j++)
#pragma unroll
            for (int q = 0; q < 4; q++) acc[i][j][q] = 0.0f;

#pragma unroll
    for (int s = 0; s < NST - 1; s++) issue(s);

    for (int it = 0; it < nIt; ++it) {
        cp_wait<NST - 2>();
        __syncthreads();
        if (it + NST - 1 < nIt) issue(it + NST - 1);

        const uint32_t stage = smb + (uint32_t)((it % NST) * STAGE);
        const uint32_t aHiB = stage
            + (uint32_t)((wr * 64 + (lane & 15)) * LDB + (lane >> 4) * 16);
        const uint32_t bHiB = stage + OFF_BHI
            + (uint32_t)((wc * (NH * 32) + lane) * LDB);

#pragma unroll
        for (int kc = 0; kc < 2; kc++) {
            uint32_t ahi[4][4], alo[4][4];
#pragma unroll
            for (int mt = 0; mt < 4; mt++) {
                ldmx4(ahi[mt], aHiB + mt * 16 * LDB + kc * 32);
                ldmx4(alo[mt], aHiB + OFF_ALO + mt * 16 * LDB + kc * 32);
            }
#pragma unroll
            for (int h = 0; h < NH; h++) {
                const uint32_t b2 = bHiB + h * 32 * LDB + kc * 32;
                uint32_t bh0[4], bh1[4], bl0[4], bl1[4];
                ldmx4(bh0, b2);
                ldmx4(bh1, b2 + 16);
                ldmx4(bl0, b2 + BLO_REL);
                ldmx4(bl1, b2 + BLO_REL + 16);
#pragma unroll
                for (int mt = 0; mt < 4; mt++)
#pragma unroll
                    for (int ntl = 0; ntl < 4; ntl++) {
                        float* d = acc[mt][h * 4 + ntl];
                        mma16816(d, ahi[mt], bh0[ntl], bh1[ntl]);
                        mma16816(d, ahi[mt], bl0[ntl], bl1[ntl]);
                        mma16816(d, alo[mt], bh0[ntl], bh1[ntl]);
                    }
            }
        }
    }

    // ---- epilogue ----
    const int er = m0 + wr * 64 + (lane >> 2);
    const int ec = n0 + wc * (NH * 32) + (lane & 3) * 2;
#pragma unroll
    for (int mt = 0; mt < 4; mt++) {
#pragma unroll
        for (int half = 0; half < 2; half++) {
            const int row = er + mt * 16 + half * 8;
            const size_t rb = (size_t)row * N;
            const float* rrow = res ? res + rb : nullptr;
#pragma unroll
            for (int nt = 0; nt < NH * 4; nt++) {
                const int col = ec + nt * 8;
                float v0 = acc[mt][nt][half * 2 + 0];
                float v1 = acc[mt][nt][half * 2 + 1];
                if (bias) { v0 += bias[col]; v1 += bias[col + 1]; }
                if (gelu) { v0 = gelu_exact(v0); v1 = gelu_exact(v1); }
                if (rrow) { v0 += rrow[col]; v1 += rrow[col + 1]; }
                if (Cf) *(float2*)(Cf + rb + col) = make_float2(v0, v1);
                if (Chi) {
                    __nv_bfloat16 h0, l0, h1, l1;
                    split1(v0, h0, l0);
                    split1(v1, h1, l1);
                    *(__nv_bfloat162*)(Chi + rb + col) = __nv_bfloat162(h0, h1);
                    *(__nv_bfloat162*)(Clo + rb + col) = __nv_bfloat162(l0, l1);
                }
            }
        }
    }
}

// ---------------------------------------------------------------------------
// Batched transpose + split: src[l][K,N] fp32 -> dhi/dlo[l][N,K] bf16
// ---------------------------------------------------------------------------
__global__ void transpose_split_b(const float* __restrict__ src,
                                  __nv_bfloat16* __restrict__ dhi,
                                  __nv_bfloat16* __restrict__ dlo,
                                  int K, int N, size_t sstride, size_t dstride)
{
    __shared__ float t[32][33];
    const int l = blockIdx.z;
    src += (size_t)l * sstride;
    dhi += (size_t)l * dstride;
    dlo += (size_t)l * dstride;
    const int k0 = blockIdx.y * 32, n0 = blockIdx.x * 32;
    const int tx = threadIdx.x, ty = threadIdx.y;   // (32, 8)
#pragma unroll
    for (int i = 0; i < 32; i += 8)
        t[ty + i][tx] = src[(size_t)(k0 + ty + i) * N + n0 + tx];
    __syncthreads();
#pragma unroll
    for (int i = 0; i < 32; i += 8) {
        float v = t[tx][ty + i];
        __nv_bfloat16 hi, lo;
        split1(v, hi, lo);
        const size_t idx = (size_t)(n0 + ty + i) * K + k0 + tx;
        dhi[idx] = hi;
        dlo[idx] = lo;
    }
}

__global__ void bias_concat(const float* __restrict__ bq, const float* __restrict__ bk,
                            const float* __restrict__ bv, float* __restrict__ dst)
{
    int l = blockIdx.y;
    int i = blockIdx.x * 256 + threadIdx.x;
    dst[l*NQKV + i]        = bq[l*DDIM + i];
    dst[l*NQKV + 1024 + i] = bk[l*DDIM + i];
    dst[l*NQKV + 2048 + i] = bv[l*DDIM + i];
}

// ---------------------------------------------------------------------------
// Embedding: x fp32 + split
// ---------------------------------------------------------------------------
__global__ void embed_kernel(const int* __restrict__ tokens,
                             const float* __restrict__ emb,
                             const float* __restrict__ pos,
                             float* __restrict__ x,
                             __nv_bfloat16* __restrict__ xhi,
                             __nv_bfloat16* __restrict__ xlo)
{
    int i = blockIdx.x;
    int s = i & (SSEQ - 1);
    int t = tokens[i];
    int d = threadIdx.x;
    const float4* e4 = (const float4*)(emb + (size_t)t * DDIM);
    const float4* p4 = (const float4*)(pos + (size_t)s * DDIM);
    float4 a = e4[d], b = p4[d];
    float4 v = make_float4(a.x + b.x, a.y + b.y, a.z + b.z, a.w + b.w);
    ((float4*)(x + (size_t)i * DDIM))[d] = v;

    __nv_bfloat16 h0,l0,h1,l1,h2,l2,h3,l3;
    split1(v.x, h0, l0); split1(v.y, h1, l1);
    split1(v.z, h2, l2); split1(v.w, h3, l3);
    __nv_bfloat162* xh = (__nv_bfloat162*)(xhi + (size_t)i * DDIM + d * 4);
    __nv_bfloat162* xl = (__nv_bfloat162*)(xlo + (size_t)i * DDIM + d * 4);
    xh[0] = __nv_bfloat162(h0, h1); xh[1] = __nv_bfloat162(h2, h3);
    xl[0] = __nv_bfloat162(l0, l1); xl[1] = __nv_bfloat162(l2, l3);
}

// ---------------------------------------------------------------------------
// Flash attention (causal), qkv packed [M,3072]; writes o split (bf16 hi/lo)
// ---------------------------------------------------------------------------
#define APAD 65
__global__ void __launch_bounds__(256)
attention_kernel(const float* __restrict__ qkv,
                 __nv_bfloat16* __restrict__ ohi, __nv_bfloat16* __restrict__ olo)
{
    extern __shared__ float smf[];
    float* Qs = smf;
    float* Ks = Qs + 64 * APAD;
    float* Vs = Ks + 64 * APAD;
    float* Ps = Vs + 64 * APAD;

    const int tid = threadIdx.x;
    const int qb  = blockIdx.x;
    const int bh  = blockIdx.y;
    const int b   = bh >> 4;
    const int h   = bh & 15;
    const size_t rowbase = (size_t)b * SSEQ;
    const int qc = h * DKV, kc = 1024 + h * DKV, vc = 2048 + h * DKV;

    const int ty = tid >> 4;
    const int tx = tid & 15;
    const float scale = 0.125f;

    for (int it = tid; it < 64 * 16; it += 256) {
        int rr = it >> 4, c4 = (it & 15) * 4;
        float4 a = *(const float4*)(qkv + (rowbase + qb*64 + rr) * NQKV + qc + c4);
        Qs[rr*APAD + c4+0] = a.x; Qs[rr*APAD + c4+1] = a.y;
        Qs[rr*APAD + c4+2] = a.z; Qs[rr*APAD + c4+3] = a.w;
    }

    float m[4], l[4], acc[4][4];
#pragma unroll
    for (int i = 0; i < 4; i++) {
        m[i] = -INFINITY; l[i] = 0.0f;
#pragma unroll
        for (int j = 0; j < 4; j++) acc[i][j] = 0.0f;
    }
    __syncthreads();

    for (int jt = 0; jt <= qb; jt++) {
        for (int it = tid; it < 64 * 16; it += 256) {
            int rr = it >> 4, c4 = (it & 15) * 4;
            const size_t grow = (rowbase + jt*64 + rr) * NQKV;
            float4 a = *(const float4*)(qkv + grow + kc + c4);
            Ks[rr*APAD + c4+0] = a.x; Ks[rr*APAD + c4+1] = a.y;
            Ks[rr*APAD + c4+2] = a.z; Ks[rr*APAD + c4+3] = a.w;
            float4 c = *(const float4*)(qkv + grow + vc + c4);
            Vs[rr*APAD + c4+0] = c.x; Vs[rr*APAD + c4+1] = c.y;
            Vs[rr*APAD + c4+2] = c.z; Vs[rr*APAD + c4+3] = c.w;
        }
        __syncthreads();

        float s[4][4];
#pragma unroll
        for (int i = 0; i < 4; i++)
#pragma unroll
            for (int j = 0; j < 4; j++) s[i][j] = 0.0f;
#pragma unroll 8
        for (int kk = 0; kk < 64; kk++) {
            float qv[4], kv[4];
#pragma unroll
            for (int i = 0; i < 4; i++) qv[i] = Qs[(ty*4+i)*APAD + kk];
#pragma unroll
            for (int j = 0; j < 4; j++) kv[j] = Ks[(tx*4+j)*APAD + kk];
#pragma unroll
            for (int i = 0; i < 4; i++)
#pragma unroll
                for (int j = 0; j < 4; j++) s[i][j] += qv[i] * kv[j];
        }

#pragma unroll
        for (int i = 0; i < 4; i++) {
            int qrow = qb*64 + ty*4 + i;
#pragma unroll
            for (int j = 0; j < 4; j++) {
                int kcol = jt*64 + tx*4 + j;
                s[i][j] = (kcol > qrow) ? -INFINITY : s[i][j] * scale;
            }
        }

#pragma unroll
        for (int i = 0; i < 4; i++) {
            float rm = fmaxf(fmaxf(s[i][0], s[i][1]), fmaxf(s[i][2], s[i][3]));
#pragma unroll
            for (int off = 1; off < 16; off <<= 1)
                rm = fmaxf(rm, __shfl_xor_sync(0xffffffffu, rm, off));
            float mnew = fmaxf(m[i], rm);
            float corr = expf(m[i] - mnew);
            l[i] *= corr;
#pragma unroll
            for (int j = 0; j < 4; j++) acc[i][j] *= corr;
            float rs = 0.0f;
#pragma unroll
            for (int j = 0; j < 4; j++) {
                float p = expf(s[i][j] - mnew);
                s[i][j] = p; rs += p;
            }
#pragma unroll
            for (int off = 1; off < 16; off <<= 1)
                rs += __shfl_xor_sync(0xffffffffu, rs, off);
            l[i] += rs; m[i] = mnew;
        }

#pragma unroll
        for (int i = 0; i < 4; i++)
#pragma unroll
            for (int j = 0; j < 4; j++)
                Ps[(ty*4+i)*APAD + tx*4 + j] = s[i][j];
        __syncthreads();

#pragma unroll 8
        for (int kk = 0; kk < 64; kk++) {
            float pv[4], vv[4];
#pragma unroll
            for (int i = 0; i < 4; i++) pv[i] = Ps[(ty*4+i)*APAD + kk];
#pragma unroll
            for (int j = 0; j < 4; j++) vv[j] = Vs[kk*APAD + tx*4 + j];
#pragma unroll
            for (int i = 0; i < 4; i++)
#pragma unroll
                for (int j = 0; j < 4; j++) acc[i][j] += pv[i] * vv[j];
        }
        __syncthreads();
    }

#pragma unroll
    for (int i = 0; i < 4; i++) {
        float inv = 1.0f / l[i];
        const size_t grow = (rowbase + qb*64 + ty*4 + i) * DDIM + h*DKV + tx*4;
        float v0 = acc[i][0]*inv, v1 = acc[i][1]*inv;
        float v2 = acc[i][2]*inv, v3 = acc[i][3]*inv;
        __nv_bfloat16 h0,l0,h1,l1,h2,l2,h3,l3;
        split1(v0, h0, l0); split1(v1, h1, l1);
        split1(v2, h2, l2); split1(v3, h3, l3);
        __nv_bfloat162* oh = (__nv_bfloat162*)(ohi + grow);
        __nv_bfloat162* ol = (__nv_bfloat162*)(olo + grow);
        oh[0] = __nv_bfloat162(h0, h1); oh[1] = __nv_bfloat162(h2, h3);
        ol[0] = __nv_bfloat162(l0, l1); ol[1] = __nv_bfloat162(l2, l3);
    }
}

// ---------------------------------------------------------------------------
// Host
// ---------------------------------------------------------------------------
#define GSMEM128 (2 * (256 + 2*128) * LDB)   // 81920
#define GSMEM256 (3 * (256 + 2*256) * LDB)   // 184320

static inline void run_gemm(const __nv_bfloat16* Ahi, const __nv_bfloat16* Alo,
                            const __nv_bfloat16* Bhi, const __nv_bfloat16* Blo,
                            const float* bias, const float* res,
                            float* Cf, __nv_bfloat16* Chi, __nv_bfloat16* Clo,
                            int M, int N, int K, int gelu, int wide)
{
    if (wide) {
        dim3 grid(N / 256, M / 128);
        gemm_pair<256,1,3><<<grid, 256, GSMEM256>>>(Ahi, Alo, Bhi, Blo, bias, res,
                                                    Cf, Chi, Clo, M, N, K, gelu);
    } else {
        dim3 grid(N / 128, M / 128);
        gemm_pair<128,2,2><<<grid, 256, GSMEM128>>>(Ahi, Alo, Bhi, Blo, bias, res,
                                                    Cf, Chi, Clo, M, N, K, gelu);
    }
}

static inline void trsb(const float* s, __nv_bfloat16* dhi, __nv_bfloat16* dlo,
                        int K, int N, size_t sstr, size_t dstr, int layers)
{
    transpose_split_b<<<dim3(N / 32, K / 32, layers), dim3(32, 8)>>>(
        s, dhi, dlo, K, N, sstr, dstr);
}

extern "C" void kernel_launch(void* const* d_in, const int* in_sizes, int n_in,
                              void* d_out, int out_size)
{
    const int*   tokens = (const int*)  d_in[0];
    const float* emb    = (const float*)d_in[1];
    const float* pos    = (const float*)d_in[2];
    const float* Wq     = (const float*)d_in[3];
    const float* bq     = (const float*)d_in[4];
    const float* Wk     = (const float*)d_in[5];
    const float* bk     = (const float*)d_in[6];
    const float* Wv     = (const float*)d_in[7];
    const float* bv     = (const float*)d_in[8];
    const float* Wo     = (const float*)d_in[9];
    const float* W1     = (const float*)d_in[10];
    const float* b1     = (const float*)d_in[11];
    const float* W2     = (const float*)d_in[12];
    const float* b2     = (const float*)d_in[13];
    const float* Wr     = (const float*)d_in[14];
    const float* br     = (const float*)d_in[15];
    float*       out    = (float*)d_out;

    float *x, *h, *qkv, *bqkv;
    __nv_bfloat16 *xhi, *xlo, *ohi, *olo, *hhi, *hlo, *thi, *tlo;
    __nv_bfloat16 *Wqkv_hi, *Wqkv_lo, *Wo_hi, *Wo_lo, *W1_hi, *W1_lo;
    __nv_bfloat16 *W2_hi, *W2_lo, *Wr_hi, *Wr_lo;
    cudaGetSymbolAddress((void**)&x,   g_x);
    cudaGetSymbolAddress((void**)&h,   g_h);
    cudaGetSymbolAddress((void**)&qkv, g_qkv);
    cudaGetSymbolAddress((void**)&bqkv, g_bqkv);
    cudaGetSymbolAddress((void**)&xhi, g_xhi);  cudaGetSymbolAddress((void**)&xlo, g_xlo);
    cudaGetSymbolAddress((void**)&ohi, g_ohi);  cudaGetSymbolAddress((void**)&olo, g_olo);
    cudaGetSymbolAddress((void**)&hhi, g_hhi);  cudaGetSymbolAddress((void**)&hlo, g_hlo);
    cudaGetSymbolAddress((void**)&thi, g_thi);  cudaGetSymbolAddress((void**)&tlo, g_tlo);
    cudaGetSymbolAddress((void**)&Wqkv_hi, g_Wqkv_hi);
    cudaGetSymbolAddress((void**)&Wqkv_lo, g_Wqkv_lo);
    cudaGetSymbolAddress((void**)&Wo_hi, g_Wo_hi);
    cudaGetSymbolAddress((void**)&Wo_lo, g_Wo_lo);
    cudaGetSymbolAddress((void**)&W1_hi, g_W1_hi);
    cudaGetSymbolAddress((void**)&W1_lo, g_W1_lo);
    cudaGetSymbolAddress((void**)&W2_hi, g_W2_hi);
    cudaGetSymbolAddress((void**)&W2_lo, g_W2_lo);
    cudaGetSymbolAddress((void**)&Wr_hi, g_Wr_hi);
    cudaGetSymbolAddress((void**)&Wr_lo, g_Wr_lo);

    cudaFuncSetAttribute((const void*)gemm_pair<128,2,2>,
                         cudaFuncAttributeMaxDynamicSharedMemorySize, GSMEM128);
    cudaFuncSetAttribute((const void*)gemm_pair<256,1,3>,
                         cudaFuncAttributeMaxDynamicSharedMemorySize, GSMEM256);
    const int ASMEM = 4 * 64 * APAD * (int)sizeof(float);
    cudaFuncSetAttribute(attention_kernel,
                         cudaFuncAttributeMaxDynamicSharedMemorySize, ASMEM);

    // weight prep (batched transpose + split), 7 launches
    const size_t DD2 = (size_t)DDIM * DDIM;
    trsb(Wq, Wqkv_hi,           Wqkv_lo,           DDIM, DDIM, DD2, (size_t)NQKV*DDIM, LLAY);
    trsb(Wk, Wqkv_hi + DD2,     Wqkv_lo + DD2,     DDIM, DDIM, DD2, (size_t)NQKV*DDIM, LLAY);
    trsb(Wv, Wqkv_hi + 2*DD2,   Wqkv_lo + 2*DD2,   DDIM, DDIM, DD2, (size_t)NQKV*DDIM, LLAY);
    trsb(Wo, Wo_hi, Wo_lo, DDIM, DDIM, DD2, DD2, LLAY);
    trsb(W1, W1_hi, W1_lo, DDIM, DHH, (size_t)DDIM*DHH, (size_t)DHH*DDIM, LLAY);
    trsb(W2, W2_hi, W2_lo, DHH, DDIM, (size_t)DHH*DDIM, (size_t)DDIM*DHH, LLAY);
    trsb(Wr, Wr_hi, Wr_lo, DDIM, VVOC, 0, 0, 1);
    bias_concat<<<dim3(4, LLAY), 256>>>(bq, bk, bv, bqkv);

    embed_kernel<<<MM, 256>>>(tokens, emb, pos, x, xhi, xlo);

    for (int l = 0; l < LLAY; l++) {
        const __nv_bfloat16* wqh = Wqkv_hi + (size_t)l*NQKV*DDIM;
        const __nv_bfloat16* wql = Wqkv_lo + (size_t)l*NQKV*DDIM;
        const __nv_bfloat16* woh = Wo_hi + (size_t)l*DDIM*DDIM;
        const __nv_bfloat16* wol = Wo_lo + (size_t)l*DDIM*DDIM;
        const __nv_bfloat16* w1h = W1_hi + (size_t)l*DHH*DDIM;
        const __nv_bfloat16* w1l = W1_lo + (size_t)l*DHH*DDIM;
        const __nv_bfloat16* w2h = W2_hi + (size_t)l*DDIM*DHH;
        const __nv_bfloat16* w2l = W2_lo + (size_t)l*DDIM*DHH;

        // qkv = x @ Wqkv + b  (fp32 out, N=3072 wide)
        run_gemm(xhi, xlo, wqh, wql, bqkv + (size_t)l*NQKV, nullptr,
                 qkv, nullptr, nullptr, MM, NQKV, DDIM, 0, 1);
        attention_kernel<<<dim3(SSEQ/64, BB*HHH), 256, ASMEM>>>(qkv, ohi, olo);
        // h = x + o @ Wo   (fp32 + split, N=1024 narrow)
        run_gemm(ohi, olo, woh, wol, nullptr, x,
                 h, hhi, hlo, MM, DDIM, DDIM, 0, 0);
        // t = gelu(h @ W1 + b1)  (split only, N=4096 wide)
        run_gemm(hhi, hlo, w1h, w1l, b1 + (size_t)l*DHH, nullptr,
                 nullptr, thi, tlo, MM, DHH, DDIM, 1, 1);
        // x = h + t @ W2 + b2  (fp32 + split, N=1024 narrow)
        run_gemm(thi, tlo, w2h, w2l, b2 + (size_t)l*DDIM, h,
                 x, xhi, xlo, MM, DDIM, DHH, 0, 0);
    }

    // out = x @ Wr + br (N=256 narrow)
    run_gemm(xhi, xlo, Wr_hi, Wr_lo, br, nullptr,
             out, nullptr, nullptr, MM, VVOC, DDIM, 0, 0);
}

// round 6
// speedup vs baseline: 1.0729x; 1.0729x over previous
#include <cuda_runtime.h>
#include <cuda_bf16.h>
#include <math.h>
#include <stdint.h>

// ---------------------------------------------------------------------------
// Problem constants
// ---------------------------------------------------------------------------
#define BB    2
#define SSEQ  1024
#define DDIM  1024
#define HHH   16
#define DKV   64
#define DHH   4096
#define LLAY  8
#define VVOC  256
#define MM    (BB*SSEQ)        // 2048
#define NQKV  3072

// ---------------------------------------------------------------------------
// Scratch (device globals: allocation-free)
// ---------------------------------------------------------------------------
__device__ float g_x   [MM*DDIM];
__device__ float g_o   [MM*DDIM];
__device__ float g_h   [MM*DDIM];
__device__ float g_t   [MM*DHH];
__device__ __nv_bfloat16 g_qkvhi[MM*NQKV], g_qkvlo[MM*NQKV];

__device__ float g_WqkvT[LLAY*NQKV*DDIM];
__device__ float g_WoT  [LLAY*DDIM*DDIM];
__device__ float g_W1T  [LLAY*DHH*DDIM];
__device__ float g_W2T  [LLAY*DDIM*DHH];
__device__ float g_WrT  [VVOC*DDIM];
__device__ float g_bqkv [LLAY*NQKV];

// ---------------------------------------------------------------------------
// Helpers
// ---------------------------------------------------------------------------
__device__ __forceinline__ uint32_t smem_u32(const void* p) {
    uint32_t a;
    asm("{ .reg .u64 t; cvta.to.shared.u64 t, %1; cvt.u32.u64 %0, t; }"
        : "=r"(a) : "l"(p));
    return a;
}

__device__ __forceinline__ void ldmx4(uint32_t* r, uint32_t addr) {
    asm volatile("ldmatrix.sync.aligned.m8n8.x4.shared.b16 {%0,%1,%2,%3}, [%4];"
        : "=r"(r[0]), "=r"(r[1]), "=r"(r[2]), "=r"(r[3]) : "r"(addr));
}

__device__ __forceinline__ void ldmx4t(uint32_t* r, uint32_t addr) {
    asm volatile("ldmatrix.sync.aligned.m8n8.x4.trans.shared.b16 {%0,%1,%2,%3}, [%4];"
        : "=r"(r[0]), "=r"(r[1]), "=r"(r[2]), "=r"(r[3]) : "r"(addr));
}

__device__ __forceinline__ void mma16816(float* d, const uint32_t* a,
                                         uint32_t b0, uint32_t b1) {
    asm volatile("mma.sync.aligned.m16n8k16.row.col.f32.bf16.bf16.f32 "
        "{%0,%1,%2,%3}, {%4,%5,%6,%7}, {%8,%9}, {%0,%1,%2,%3};"
        : "+f"(d[0]), "+f"(d[1]), "+f"(d[2]), "+f"(d[3])
        : "r"(a[0]), "r"(a[1]), "r"(a[2]), "r"(a[3]), "r"(b0), "r"(b1));
}

__device__ __forceinline__ void cp16(uint32_t dst, const void* src) {
    asm volatile("cp.async.cg.shared.global [%0], [%1], 16;"
        :: "r"(dst), "l"(src) : "memory");
}
#define CP_COMMIT() asm volatile("cp.async.commit_group;" ::: "memory")
#define CP_WAIT0()  asm volatile("cp.async.wait_group 0;" ::: "memory")

__device__ __forceinline__ float gelu_exact(float v) {
    return 0.5f * v * (1.0f + erff(v * 0.70710678118654752f));
}

__device__ __forceinline__ void split_f4(float4 v, uint2& hi, uint2& lo) {
    __nv_bfloat16 b0 = __float2bfloat16(v.x);
    __nv_bfloat16 b1 = __float2bfloat16(v.y);
    __nv_bfloat16 b2 = __float2bfloat16(v.z);
    __nv_bfloat16 b3 = __float2bfloat16(v.w);
    float r0 = v.x - __bfloat162float(b0);
    float r1 = v.y - __bfloat162float(b1);
    float r2 = v.z - __bfloat162float(b2);
    float r3 = v.w - __bfloat162float(b3);
    hi.x = ((uint32_t)__bfloat16_as_ushort(b1) << 16) | __bfloat16_as_ushort(b0);
    hi.y = ((uint32_t)__bfloat16_as_ushort(b3) << 16) | __bfloat16_as_ushort(b2);
    __nv_bfloat162 l01 = __floats2bfloat162_rn(r0, r1);
    __nv_bfloat162 l23 = __floats2bfloat162_rn(r2, r3);
    lo.x = *(uint32_t*)&l01;
    lo.y = *(uint32_t*)&l23;
}

__device__ __forceinline__ void split1(float v, __nv_bfloat16& hi, __nv_bfloat16& lo) {
    hi = __float2bfloat16(v);
    lo = __float2bfloat16(v - __bfloat162float(hi));
}

// ---------------------------------------------------------------------------
// GEMM (R3-proven): C = act(A @ Bt^T + bias) + res; A,Bt fp32; split in-kernel.
// bf16x3 via mma.sync m16n8k16. 128x128 tile, BK=32, 8 warps, double-buffer.
// Output: fp32 Cf and/or bf16 hi/lo pair (Chi,Clo).
// ---------------------------------------------------------------------------
#define LDB        80
#define TILE_B     (128*LDB)
#define OFF_AHI    0
#define OFF_ALO    (1*TILE_B)
#define OFF_BHI    (2*TILE_B)
#define OFF_BLO    (3*TILE_B)
#define STAGE_B    (4*TILE_B)
#define GSMEM      (2*STAGE_B)

__global__ void __launch_bounds__(256)
gemm_mma(const float* __restrict__ A, const float* __restrict__ Bt,
         const float* __restrict__ bias, const float* __restrict__ res,
         float* __restrict__ Cf,
         __nv_bfloat16* __restrict__ Chi, __nv_bfloat16* __restrict__ Clo,
         int M, int N, int K, int gelu)
{
    extern __shared__ char sm[];
    const uint32_t smb = smem_u32(sm);

    const int tid  = threadIdx.x;
    const int lane = tid & 31;
    const int wid  = tid >> 5;
    const int wr   = wid >> 2;
    const int wc   = wid & 3;
    const int m0   = blockIdx.y * 128;
    const int n0   = blockIdx.x * 128;

    const int sc4  = tid & 7;
    const int srow = tid >> 3;
    const float* aP = A  + (size_t)(m0 + srow) * K + sc4 * 4;
    const float* bP = Bt + (size_t)(n0 + srow) * K + sc4 * 4;

    float acc[4][4][4];
#pragma unroll
    for (int i = 0; i < 4; i++)
#pragma unroll
        for (int j = 0; j < 4; j++)
#pragma unroll
            for (int q = 0; q < 4; q++) acc[i][j][q] = 0.0f;

    float4 ra[4], rb[4];
#pragma unroll
    for (int p = 0; p < 4; p++) {
        ra[p] = __ldg((const float4*)(aP + (size_t)p * 32 * K));
        rb[p] = __ldg((const float4*)(bP + (size_t)p * 32 * K));
    }
    {
        char* sp = sm;
#pragma unroll
        for (int p = 0; p < 4; p++) {
            uint32_t off = (uint32_t)((srow + p * 32) * LDB + sc4 * 8);
            uint2 hi, lo;
            split_f4(ra[p], hi, lo);
            *(uint2*)(sp + OFF_AHI + off) = hi;
            *(uint2*)(sp + OFF_ALO + off) = lo;
            split_f4(rb[p], hi, lo);
            *(uint2*)(sp + OFF_BHI + off) = hi;
            *(uint2*)(sp + OFF_BLO + off) = lo;
        }
    }
    __syncthreads();

    const int nIt = K >> 5;
    for (int it = 0; it < nIt; ++it) {
        const int cur = it & 1;

        if (it + 1 < nIt) {
#pragma unroll
            for (int p = 0; p < 4; p++) {
                ra[p] = __ldg((const float4*)(aP + (it + 1) * 32 + (size_t)p * 32 * K));
                rb[p] = __ldg((const float4*)(bP + (it + 1) * 32 + (size_t)p * 32 * K));
            }
        }

        const uint32_t stage = smb + cur * STAGE_B;
        const uint32_t aHiB = stage + OFF_AHI + (uint32_t)((wr * 64 + (lane & 15)) * LDB + (lane >> 4) * 16);
        const uint32_t aLoB = aHiB + TILE_B;
        const uint32_t bHiB = stage + OFF_BHI + (uint32_t)((wc * 32 + lane) * LDB);
        const uint32_t bLoB = bHiB + TILE_B;

#pragma unroll
        for (int kc = 0; kc < 2; kc++) {
            uint32_t ahi[4][4], alo[4][4];
            uint32_t bh0[4], bh1[4], bl0[4], bl1[4];
#pragma unroll
            for (int mt = 0; mt < 4; mt++) {
                ldmx4(ahi[mt], aHiB + mt * 16 * LDB + kc * 32);
                ldmx4(alo[mt], aLoB + mt * 16 * LDB + kc * 32);
            }
            ldmx4(bh0, bHiB + kc * 32);
            ldmx4(bh1, bHiB + kc * 32 + 16);
            ldmx4(bl0, bLoB + kc * 32);
            ldmx4(bl1, bLoB + kc * 32 + 16);

#pragma unroll
            for (int mt = 0; mt < 4; mt++)
#pragma unroll
                for (int nt = 0; nt < 4; nt++) {
                    mma16816(acc[mt][nt], ahi[mt], bh0[nt], bh1[nt]);
                    mma16816(acc[mt][nt], ahi[mt], bl0[nt], bl1[nt]);
                    mma16816(acc[mt][nt], alo[mt], bh0[nt], bh1[nt]);
                }
        }

        if (it + 1 < nIt) {
            char* sp = sm + ((it + 1) & 1) * STAGE_B;
#pragma unroll
            for (int p = 0; p < 4; p++) {
                uint32_t off = (uint32_t)((srow + p * 32) * LDB + sc4 * 8);
                uint2 hi, lo;
                split_f4(ra[p], hi, lo);
                *(uint2*)(sp + OFF_AHI + off) = hi;
                *(uint2*)(sp + OFF_ALO + off) = lo;
                split_f4(rb[p], hi, lo);
                *(uint2*)(sp + OFF_BHI + off) = hi;
                *(uint2*)(sp + OFF_BLO + off) = lo;
            }
        }
        __syncthreads();
    }

    // ---- epilogue ----
    const int er = m0 + wr * 64 + (lane >> 2);
    const int ec = n0 + wc * 32 + (lane & 3) * 2;
#pragma unroll
    for (int mt = 0; mt < 4; mt++) {
#pragma unroll
        for (int half = 0; half < 2; half++) {
            const int row = er + mt * 16 + half * 8;
            const size_t rb2 = (size_t)row * N;
            const float* rrow = res ? res + rb2 : nullptr;
#pragma unroll
            for (int nt = 0; nt < 4; nt++) {
                const int col = ec + nt * 8;
                float v0 = acc[mt][nt][half * 2 + 0];
                float v1 = acc[mt][nt][half * 2 + 1];
                if (bias) { v0 += bias[col]; v1 += bias[col + 1]; }
                if (gelu) { v0 = gelu_exact(v0); v1 = gelu_exact(v1); }
                if (rrow) { v0 += rrow[col]; v1 += rrow[col + 1]; }
                if (Cf) *(float2*)(Cf + rb2 + col) = make_float2(v0, v1);
                if (Chi) {
                    __nv_bfloat16 h0, l0, h1, l1;
                    split1(v0, h0, l0);
                    split1(v1, h1, l1);
                    *(__nv_bfloat162*)(Chi + rb2 + col) = __nv_bfloat162(h0, h1);
                    *(__nv_bfloat162*)(Clo + rb2 + col) = __nv_bfloat162(l0, l1);
                }
            }
        }
    }
}

// ---------------------------------------------------------------------------
// Transpose src[K,N] -> dst[N,K] (fp32, 32x32 tiles)
// ---------------------------------------------------------------------------
__global__ void transpose32(const float* __restrict__ src, float* __restrict__ dst,
                            int K, int N)
{
    __shared__ float t[32][33];
    const int k0 = blockIdx.y * 32, n0 = blockIdx.x * 32;
    const int tx = threadIdx.x, ty = threadIdx.y;
#pragma unroll
    for (int i = 0; i < 32; i += 8)
        t[ty + i][tx] = src[(size_t)(k0 + ty + i) * N + n0 + tx];
    __syncthreads();
#pragma unroll
    for (int i = 0; i < 32; i += 8)
        dst[(size_t)(n0 + ty + i) * K + k0 + tx] = t[tx][ty + i];
}

__global__ void bias_concat(const float* __restrict__ bq, const float* __restrict__ bk,
                            const float* __restrict__ bv, float* __restrict__ dst)
{
    int l = blockIdx.y;
    int i = blockIdx.x * 256 + threadIdx.x;
    dst[l*NQKV + i]        = bq[l*DDIM + i];
    dst[l*NQKV + 1024 + i] = bk[l*DDIM + i];
    dst[l*NQKV + 2048 + i] = bv[l*DDIM + i];
}

__global__ void embed_kernel(const int* __restrict__ tokens,
                             const float* __restrict__ emb,
                             const float* __restrict__ pos,
                             float* __restrict__ x)
{
    int i = blockIdx.x;
    int s = i & (SSEQ - 1);
    int t = tokens[i];
    const float4* e4 = (const float4*)(emb + (size_t)t * DDIM);
    const float4* p4 = (const float4*)(pos + (size_t)s * DDIM);
    float4*       x4 = (float4*)(x + (size_t)i * DDIM);
    int d = threadIdx.x;
    float4 a = e4[d], b = p4[d];
    x4[d] = make_float4(a.x + b.x, a.y + b.y, a.z + b.z, a.w + b.w);
}

// ---------------------------------------------------------------------------
// Tensor-core flash attention (causal), bf16x3 split precision.
// qkv given as bf16 hi/lo pairs, packed [M, 3072] (q@h*64, k@1024+h*64, v@2048+).
// Per CTA: one (b,h), 128 Q rows, KV tiles of 64. 8 warps, warp = 16 Q rows.
// Writes fp32 o [M, 1024].
// ---------------------------------------------------------------------------
#define ALDB  144                      // smem row stride bytes (72 bf16)
#define AQHI  0
#define AQLO  18432                    // 128*144
#define AKHI  36864
#define AARR  9216                     // 64*144 (KHI,KLO,VHI,VLO spacing)
#define ASMEM 73728

__global__ void __launch_bounds__(256, 2)
attn_mma(const __nv_bfloat16* __restrict__ qkvhi,
         const __nv_bfloat16* __restrict__ qkvlo,
         float* __restrict__ o)
{
    extern __shared__ char sm[];
    const uint32_t smb = smem_u32(sm);

    const int tid  = threadIdx.x;
    const int lane = tid & 31;
    const int w    = tid >> 5;
    const int qb   = blockIdx.x;       // 0..7 (128-row Q tiles)
    const int bh   = blockIdx.y;       // 0..31
    const int b    = bh >> 4;
    const int h    = bh & 15;
    const int rowbase = b * SSEQ;
    const int qc = h * DKV, kc = 1024 + h * DKV, vc = 2048 + h * DKV;

    // ---- load Q tile (128 rows x 64 bf16, hi+lo) ----
    {
        const int ch  = tid & 7;            // 16B chunk within row
        const int wh  = (tid >> 3) & 1;     // hi/lo
        const __nv_bfloat16* src = (wh ? qkvlo : qkvhi);
        const uint32_t dstb = smb + (wh ? AQLO : AQHI) + ch * 16;
#pragma unroll
        for (int i = 0; i < 8; i++) {
            const int r = i * 16 + (tid >> 4);
            cp16(dstb + r * ALDB,
                 src + (size_t)(rowbase + qb * 128 + r) * NQKV + qc + ch * 8);
        }
        CP_COMMIT();
    }

    float sO[8][4];
#pragma unroll
    for (int i = 0; i < 8; i++)
#pragma unroll
        for (int q = 0; q < 4; q++) sO[i][q] = 0.0f;
    float mrow[2] = { -INFINITY, -INFINITY };
    float lrow[2] = { 0.0f, 0.0f };

    // per-thread KV staging constants
    const int ch  = tid & 7;
    const int arr = (tid >> 3) & 3;        // 0:Khi 1:Klo 2:Vhi 3:Vlo
    const __nv_bfloat16* kvsrc =
        (arr == 0) ? qkvhi : (arr == 1) ? qkvlo : (arr == 2) ? qkvhi : qkvlo;
    const int kvcol = (arr < 2) ? kc : vc;
    const uint32_t kvdstb = smb + AKHI + arr * AARR + ch * 16;

    const int ntile = 2 * (qb + 1);
    for (int kt = 0; kt < ntile; kt++) {
        __syncthreads();   // all warps done with previous tile's smem
        {
#pragma unroll
            for (int i = 0; i < 8; i++) {
                const int r = i * 8 + (tid >> 5);
                cp16(kvdstb + r * ALDB,
                     kvsrc + (size_t)(rowbase + kt * 64 + r) * NQKV + kvcol + ch * 8);
            }
            CP_COMMIT();
        }
        CP_WAIT0();
        __syncthreads();

        // ---- QK^T: scores s[8][4] = 16x64 per warp ----
        float s[8][4];
#pragma unroll
        for (int i = 0; i < 8; i++)
#pragma unroll
            for (int q = 0; q < 4; q++) s[i][q] = 0.0f;

        const uint32_t qHiB = smb + AQHI
            + (uint32_t)((w * 16 + (lane & 15)) * ALDB + (lane >> 4) * 16);
        const uint32_t kHiB0 = smb + AKHI + (uint32_t)(lane * ALDB);

#pragma unroll
        for (int ks = 0; ks < 4; ks++) {
            uint32_t aH[4], aL[4];
            ldmx4(aH, qHiB + ks * 32);
            ldmx4(aL, qHiB + (AQLO - AQHI) + ks * 32);
#pragma unroll
            for (int nb = 0; nb < 2; nb++) {
                const uint32_t kb = kHiB0 + nb * 32 * ALDB + ks * 32;
                uint32_t bh0[4], bh1[4], bl0[4], bl1[4];
                ldmx4(bh0, kb);
                ldmx4(bh1, kb + 16);
                ldmx4(bl0, kb + AARR);
                ldmx4(bl1, kb + AARR + 16);
#pragma unroll
                for (int nt = 0; nt < 4; nt++) {
                    float* d = s[nb * 4 + nt];
                    mma16816(d, aH, bh0[nt], bh1[nt]);
                    mma16816(d, aH, bl0[nt], bl1[nt]);
                    mma16816(d, aL, bh0[nt], bh1[nt]);
                }
            }
        }

        // ---- scale + causal mask ----
        const int r0 = qb * 128 + w * 16 + (lane >> 2);
        const int c0 = kt * 64 + (lane & 3) * 2;
#pragma unroll
        for (int nf = 0; nf < 8; nf++) {
            const int col = c0 + nf * 8;
#pragma unroll
            for (int q = 0; q < 4; q++) {
                const int row = r0 + (q >> 1) * 8;
                const int cc  = col + (q & 1);
                float v = s[nf][q] * 0.125f;
                s[nf][q] = (cc > row) ? -INFINITY : v;
            }
        }

        // ---- online softmax (2 rows per thread) ----
        float mx0 = s[0][0], mx1 = s[0][2];
#pragma unroll
        for (int nf = 0; nf < 8; nf++) {
            mx0 = fmaxf(mx0, fmaxf(s[nf][0], s[nf][1]));
            mx1 = fmaxf(mx1, fmaxf(s[nf][2], s[nf][3]));
        }
        mx0 = fmaxf(mx0, __shfl_xor_sync(0xffffffffu, mx0, 1));
        mx0 = fmaxf(mx0, __shfl_xor_sync(0xffffffffu, mx0, 2));
        mx1 = fmaxf(mx1, __shfl_xor_sync(0xffffffffu, mx1, 1));
        mx1 = fmaxf(mx1, __shfl_xor_sync(0xffffffffu, mx1, 2));

        const float mn0 = fmaxf(mrow[0], mx0);
        const float mn1 = fmaxf(mrow[1], mx1);
        const float co0 = __expf(mrow[0] - mn0);
        const float co1 = __expf(mrow[1] - mn1);
        lrow[0] *= co0; lrow[1] *= co1;
#pragma unroll
        for (int nf = 0; nf < 8; nf++) {
            sO[nf][0] *= co0; sO[nf][1] *= co0;
            sO[nf][2] *= co1; sO[nf][3] *= co1;
        }
        float su0 = 0.0f, su1 = 0.0f;
#pragma unroll
        for (int nf = 0; nf < 8; nf++) {
            s[nf][0] = __expf(s[nf][0] - mn0); su0 += s[nf][0];
            s[nf][1] = __expf(s[nf][1] - mn0); su0 += s[nf][1];
            s[nf][2] = __expf(s[nf][2] - mn1); su1 += s[nf][2];
            s[nf][3] = __expf(s[nf][3] - mn1); su1 += s[nf][3];
        }
        su0 += __shfl_xor_sync(0xffffffffu, su0, 1);
        su0 += __shfl_xor_sync(0xffffffffu, su0, 2);
        su1 += __shfl_xor_sync(0xffffffffu, su1, 1);
        su1 += __shfl_xor_sync(0xffffffffu, su1, 2);
        lrow[0] += su0; lrow[1] += su1;
        mrow[0] = mn0; mrow[1] = mn1;

        // ---- P @ V ----
        const uint32_t vHiB0 = smb + AKHI + 2 * AARR
            + (uint32_t)((lane & 15) * ALDB + (lane >> 4) * 16);
#pragma unroll
        for (int ks = 0; ks < 4; ks++) {
            // P fragments (bf16 hi/lo) from score regs, FA2 layout reuse
            uint32_t pa_h[4], pa_l[4];
            {
                __nv_bfloat16 h0, l0, h1, l1;
                split1(s[2*ks][0], h0, l0); split1(s[2*ks][1], h1, l1);
                pa_h[0] = ((uint32_t)__bfloat16_as_ushort(h1) << 16) | __bfloat16_as_ushort(h0);
                pa_l[0] = ((uint32_t)__bfloat16_as_ushort(l1) << 16) | __bfloat16_as_ushort(l0);
                split1(s[2*ks][2], h0, l0); split1(s[2*ks][3], h1, l1);
                pa_h[1] = ((uint32_t)__bfloat16_as_ushort(h1) << 16) | __bfloat16_as_ushort(h0);
                pa_l[1] = ((uint32_t)__bfloat16_as_ushort(l1) << 16) | __bfloat16_as_ushort(l0);
                split1(s[2*ks+1][0], h0, l0); split1(s[2*ks+1][1], h1, l1);
                pa_h[2] = ((uint32_t)__bfloat16_as_ushort(h1) << 16) | __bfloat16_as_ushort(h0);
                pa_l[2] = ((uint32_t)__bfloat16_as_ushort(l1) << 16) | __bfloat16_as_ushort(l0);
                split1(s[2*ks+1][2], h0, l0); split1(s[2*ks+1][3], h1, l1);
                pa_h[3] = ((uint32_t)__bfloat16_as_ushort(h1) << 16) | __bfloat16_as_ushort(h0);
                pa_l[3] = ((uint32_t)__bfloat16_as_ushort(l1) << 16) | __bfloat16_as_ushort(l0);
            }
#pragma unroll
            for (int nb = 0; nb < 4; nb++) {
                const uint32_t vb = vHiB0 + ks * 16 * ALDB + nb * 32;
                uint32_t vh[4], vl[4];
                ldmx4t(vh, vb);
                ldmx4t(vl, vb + AARR);
                float* d0 = sO[nb * 2];
                float* d1 = sO[nb * 2 + 1];
                mma16816(d0, pa_h, vh[0], vh[1]);
                mma16816(d0, pa_h, vl[0], vl[1]);
                mma16816(d0, pa_l, vh[0], vh[1]);
                mma16816(d1, pa_h, vh[2], vh[3]);
                mma16816(d1, pa_h, vl[2], vl[3]);
                mma16816(d1, pa_l, vh[2], vh[3]);
            }
        }
    }

    // ---- epilogue: O = acc / l -> fp32 o[M, 1024] ----
    const float inv0 = 1.0f / lrow[0];
    const float inv1 = 1.0f / lrow[1];
    const int gr0 = rowbase + qb * 128 + w * 16 + (lane >> 2);
    const int colb = h * DKV + (lane & 3) * 2;
#pragma unroll
    for (int nf = 0; nf < 8; nf++) {
        const int col = colb + nf * 8;
        *(float2*)(o + (size_t)gr0 * DDIM + col) =
            make_float2(sO[nf][0] * inv0, sO[nf][1] * inv0);
        *(float2*)(o + (size_t)(gr0 + 8) * DDIM + col) =
            make_float2(sO[nf][2] * inv1, sO[nf][3] * inv1);
    }
}

// ---------------------------------------------------------------------------
// Host
// ---------------------------------------------------------------------------
static inline void run_gemm(const float* A, const float* Bt, const float* bias,
                            const float* res, float* Cf,
                            __nv_bfloat16* Chi, __nv_bfloat16* Clo,
                            int M, int N, int K, int gelu)
{
    dim3 grid(N / 128, M / 128);
    gemm_mma<<<grid, 256, GSMEM>>>(A, Bt, bias, res, Cf, Chi, Clo, M, N, K, gelu);
}

static inline void tr(const float* s, float* d, int K, int N)
{
    transpose32<<<dim3(N / 32, K / 32), dim3(32, 8)>>>(s, d, K, N);
}

extern "C" void kernel_launch(void* const* d_in, const int* in_sizes, int n_in,
                              void* d_out, int out_size)
{
    const int*   tokens = (const int*)  d_in[0];
    const float* emb    = (const float*)d_in[1];
    const float* pos    = (const float*)d_in[2];
    const float* Wq     = (const float*)d_in[3];
    const float* bq     = (const float*)d_in[4];
    const float* Wk     = (const float*)d_in[5];
    const float* bk     = (const float*)d_in[6];
    const float* Wv     = (const float*)d_in[7];
    const float* bv     = (const float*)d_in[8];
    const float* Wo     = (const float*)d_in[9];
    const float* W1     = (const float*)d_in[10];
    const float* b1     = (const float*)d_in[11];
    const float* W2     = (const float*)d_in[12];
    const float* b2     = (const float*)d_in[13];
    const float* Wr     = (const float*)d_in[14];
    const float* br     = (const float*)d_in[15];
    float*       out    = (float*)d_out;

    float *x, *o, *h, *t, *bqkv;
    __nv_bfloat16 *qkvhi, *qkvlo;
    float *WqkvT, *WoT, *W1T, *W2T, *WrT;
    cudaGetSymbolAddress((void**)&x,     g_x);
    cudaGetSymbolAddress((void**)&o,     g_o);
    cudaGetSymbolAddress((void**)&h,     g_h);
    cudaGetSymbolAddress((void**)&t,     g_t);
    cudaGetSymbolAddress((void**)&qkvhi, g_qkvhi);
    cudaGetSymbolAddress((void**)&qkvlo, g_qkvlo);
    cudaGetSymbolAddress((void**)&WqkvT, g_WqkvT);
    cudaGetSymbolAddress((void**)&WoT,   g_WoT);
    cudaGetSymbolAddress((void**)&W1T,   g_W1T);
    cudaGetSymbolAddress((void**)&W2T,   g_W2T);
    cudaGetSymbolAddress((void**)&WrT,   g_WrT);
    cudaGetSymbolAddress((void**)&bqkv,  g_bqkv);

    cudaFuncSetAttribute(gemm_mma,
                         cudaFuncAttributeMaxDynamicSharedMemorySize, GSMEM);
    cudaFuncSetAttribute(attn_mma,
                         cudaFuncAttributeMaxDynamicSharedMemorySize, ASMEM);

    // --- launches 1-5 (so ncu -s5 -c1 captures the wide QKV GEMM) ---
    tr(Wq, WqkvT + 0*(size_t)DDIM*DDIM, DDIM, DDIM);            // layer 0 Wq
    tr(Wk, WqkvT + 1*(size_t)DDIM*DDIM, DDIM, DDIM);            // layer 0 Wk
    tr(Wv, WqkvT + 2*(size_t)DDIM*DDIM, DDIM, DDIM);            // layer 0 Wv
    bias_concat<<<dim3(4, LLAY), 256>>>(bq, bk, bv, bqkv);
    embed_kernel<<<MM, 256>>>(tokens, emb, pos, x);

    // --- launch 6: layer-0 QKV GEMM (profiled) ---
    run_gemm(x, WqkvT, bqkv, nullptr, nullptr, qkvhi, qkvlo, MM, NQKV, DDIM, 0);

    // --- remaining weight prep ---
    for (int l = 1; l < LLAY; l++) {
        tr(Wq + (size_t)l*DDIM*DDIM, WqkvT + (size_t)l*NQKV*DDIM + 0*(size_t)DDIM*DDIM, DDIM, DDIM);
        tr(Wk + (size_t)l*DDIM*DDIM, WqkvT + (size_t)l*NQKV*DDIM + 1*(size_t)DDIM*DDIM, DDIM, DDIM);
        tr(Wv + (size_t)l*DDIM*DDIM, WqkvT + (size_t)l*NQKV*DDIM + 2*(size_t)DDIM*DDIM, DDIM, DDIM);
    }
    for (int l = 0; l < LLAY; l++) {
        tr(Wo + (size_t)l*DDIM*DDIM, WoT + (size_t)l*DDIM*DDIM, DDIM, DDIM);
        tr(W1 + (size_t)l*DDIM*DHH,  W1T + (size_t)l*DHH*DDIM,  DDIM, DHH);
        tr(W2 + (size_t)l*DHH*DDIM,  W2T + (size_t)l*DDIM*DHH,  DHH,  DDIM);
    }
    tr(Wr, WrT, DDIM, VVOC);

    for (int l = 0; l < LLAY; l++) {
        const float* woT = WoT + (size_t)l*DDIM*DDIM;
        const float* w1T = W1T + (size_t)l*DHH*DDIM;
        const float* w2T = W2T + (size_t)l*DDIM*DHH;

        if (l > 0) {
            run_gemm(x, WqkvT + (size_t)l*NQKV*DDIM, bqkv + (size_t)l*NQKV, nullptr,
                     nullptr, qkvhi, qkvlo, MM, NQKV, DDIM, 0);
        }
        attn_mma<<<dim3(SSEQ/128, BB*HHH), 256, ASMEM>>>(qkvhi, qkvlo, o);
        // h = x + o @ Wo
        run_gemm(o, woT, nullptr, x, h, nullptr, nullptr, MM, DDIM, DDIM, 0);
        // t = gelu(h @ W1 + b1)
        run_gemm(h, w1T, b1 + (size_t)l*DHH, nullptr, t, nullptr, nullptr, MM, DHH, DDIM, 1);
        // x = h + t @ W2 + b2
        run_gemm(t, w2T, b2 + (size_t)l*DDIM, h, x, nullptr, nullptr, MM, DDIM, DHH, 0);
    }

    // out = x @ Wr + br
    run_gemm(x, WrT, br, nullptr, out, nullptr, nullptr, MM, VVOC, DDIM, 0);
}

// round 7
// speedup vs baseline: 1.2528x; 1.1677x over previous
#include <cuda_runtime.h>
#include <cuda_bf16.h>
#include <math.h>
#include <stdint.h>

// ---------------------------------------------------------------------------
// Problem constants
// ---------------------------------------------------------------------------
#define BB    2
#define SSEQ  1024
#define DDIM  1024
#define HHH   16
#define DKV   64
#define DHH   4096
#define LLAY  8
#define VVOC  256
#define MM    (BB*SSEQ)        // 2048
#define NQKV  3072

// ---------------------------------------------------------------------------
// Scratch (device globals: allocation-free)
// ---------------------------------------------------------------------------
__device__ float g_x   [MM*DDIM];
__device__ float g_o   [MM*DDIM];
__device__ float g_h   [MM*DDIM];
__device__ float g_t   [MM*DHH];
__device__ __nv_bfloat16 g_qkvhi[MM*NQKV], g_qkvlo[MM*NQKV];

__device__ float g_WqkvT[LLAY*NQKV*DDIM];
__device__ float g_WoT  [LLAY*DDIM*DDIM];
__device__ float g_W1T  [LLAY*DHH*DDIM];
__device__ float g_W2T  [LLAY*DDIM*DHH];
__device__ float g_WrT  [VVOC*DDIM];
__device__ float g_bqkv [LLAY*NQKV];

// ---------------------------------------------------------------------------
// Helpers
// ---------------------------------------------------------------------------
__device__ __forceinline__ uint32_t smem_u32(const void* p) {
    uint32_t a;
    asm("{ .reg .u64 t; cvta.to.shared.u64 t, %1; cvt.u32.u64 %0, t; }"
        : "=r"(a) : "l"(p));
    return a;
}

__device__ __forceinline__ void ldmx4(uint32_t* r, uint32_t addr) {
    asm volatile("ldmatrix.sync.aligned.m8n8.x4.shared.b16 {%0,%1,%2,%3}, [%4];"
        : "=r"(r[0]), "=r"(r[1]), "=r"(r[2]), "=r"(r[3]) : "r"(addr));
}

__device__ __forceinline__ void ldmx4t(uint32_t* r, uint32_t addr) {
    asm volatile("ldmatrix.sync.aligned.m8n8.x4.trans.shared.b16 {%0,%1,%2,%3}, [%4];"
        : "=r"(r[0]), "=r"(r[1]), "=r"(r[2]), "=r"(r[3]) : "r"(addr));
}

__device__ __forceinline__ void mma16816(float* d, const uint32_t* a,
                                         uint32_t b0, uint32_t b1) {
    asm volatile("mma.sync.aligned.m16n8k16.row.col.f32.bf16.bf16.f32 "
        "{%0,%1,%2,%3}, {%4,%5,%6,%7}, {%8,%9}, {%0,%1,%2,%3};"
        : "+f"(d[0]), "+f"(d[1]), "+f"(d[2]), "+f"(d[3])
        : "r"(a[0]), "r"(a[1]), "r"(a[2]), "r"(a[3]), "r"(b0), "r"(b1));
}

__device__ __forceinline__ void cp16(uint32_t dst, const void* src) {
    asm volatile("cp.async.cg.shared.global [%0], [%1], 16;"
        :: "r"(dst), "l"(src) : "memory");
}
#define CP_COMMIT() asm volatile("cp.async.commit_group;" ::: "memory")
#define CP_WAIT0()  asm volatile("cp.async.wait_group 0;" ::: "memory")

__device__ __forceinline__ float gelu_exact(float v) {
    return 0.5f * v * (1.0f + erff(v * 0.70710678118654752f));
}

__device__ __forceinline__ void split_f4(float4 v, uint2& hi, uint2& lo) {
    __nv_bfloat16 b0 = __float2bfloat16(v.x);
    __nv_bfloat16 b1 = __float2bfloat16(v.y);
    __nv_bfloat16 b2 = __float2bfloat16(v.z);
    __nv_bfloat16 b3 = __float2bfloat16(v.w);
    float r0 = v.x - __bfloat162float(b0);
    float r1 = v.y - __bfloat162float(b1);
    float r2 = v.z - __bfloat162float(b2);
    float r3 = v.w - __bfloat162float(b3);
    hi.x = ((uint32_t)__bfloat16_as_ushort(b1) << 16) | __bfloat16_as_ushort(b0);
    hi.y = ((uint32_t)__bfloat16_as_ushort(b3) << 16) | __bfloat16_as_ushort(b2);
    __nv_bfloat162 l01 = __floats2bfloat162_rn(r0, r1);
    __nv_bfloat162 l23 = __floats2bfloat162_rn(r2, r3);
    lo.x = *(uint32_t*)&l01;
    lo.y = *(uint32_t*)&l23;
}

__device__ __forceinline__ void split1(float v, __nv_bfloat16& hi, __nv_bfloat16& lo) {
    hi = __float2bfloat16(v);
    lo = __float2bfloat16(v - __bfloat162float(hi));
}

// ---------------------------------------------------------------------------
// GEMM: C = act(A @ Bt^T + bias) + res; fp32 in, bf16x3 split in-kernel.
// BM in {128, 64}; BN = 128; BK = 32; 8 warps; double-buffered smem.
// BM=128: warp tile 64x32 (R3-proven heavy config, 1 CTA/SM).
// BM=64 : warp tile 32x32, <=128 regs, 2 CTAs/SM (for N=1024 GEMMs).
// ---------------------------------------------------------------------------
#define LDB 80

template<int BM, int MINB>
__global__ void __launch_bounds__(256, MINB)
gemm_mma(const float* __restrict__ A, const float* __restrict__ Bt,
         const float* __restrict__ bias, const float* __restrict__ res,
         float* __restrict__ Cf,
         __nv_bfloat16* __restrict__ Chi, __nv_bfloat16* __restrict__ Clo,
         int M, int N, int K, int gelu)
{
    constexpr int MT      = BM / 32;        // A frags per warp (4 or 2)
    constexpr int AP      = BM / 32;        // A staging chunks per thread
    constexpr int ATILE   = BM * LDB;
    constexpr int OFF_ALO = ATILE;
    constexpr int OFF_BHI = 2 * ATILE;
    constexpr int OFF_BLO = 2 * ATILE + 128 * LDB;
    constexpr int STAGE   = (2 * BM + 256) * LDB;

    extern __shared__ char sm[];
    const uint32_t smb = smem_u32(sm);

    const int tid  = threadIdx.x;
    const int lane = tid & 31;
    const int wid  = tid >> 5;
    const int wr   = wid >> 2;
    const int wc   = wid & 3;
    const int m0   = blockIdx.y * BM;
    const int n0   = blockIdx.x * 128;

    const int sc4  = tid & 7;
    const int srow = tid >> 3;
    const float* aP = A  + (size_t)(m0 + srow) * K + sc4 * 4;
    const float* bP = Bt + (size_t)(n0 + srow) * K + sc4 * 4;

    float acc[MT][4][4];
#pragma unroll
    for (int i = 0; i < MT; i++)
#pragma unroll
        for (int j = 0; j < 4; j++)
#pragma unroll
            for (int q = 0; q < 4; q++) acc[i][j][q] = 0.0f;

    float4 ra[AP], rb[4];
#pragma unroll
    for (int p = 0; p < AP; p++)
        ra[p] = __ldg((const float4*)(aP + (size_t)p * 32 * K));
#pragma unroll
    for (int p = 0; p < 4; p++)
        rb[p] = __ldg((const float4*)(bP + (size_t)p * 32 * K));
    {
        char* sp = sm;
#pragma unroll
        for (int p = 0; p < AP; p++) {
            uint32_t off = (uint32_t)((srow + p * 32) * LDB + sc4 * 8);
            uint2 hi, lo;
            split_f4(ra[p], hi, lo);
            *(uint2*)(sp + off) = hi;
            *(uint2*)(sp + OFF_ALO + off) = lo;
        }
#pragma unroll
        for (int p = 0; p < 4; p++) {
            uint32_t off = (uint32_t)((srow + p * 32) * LDB + sc4 * 8);
            uint2 hi, lo;
            split_f4(rb[p], hi, lo);
            *(uint2*)(sp + OFF_BHI + off) = hi;
            *(uint2*)(sp + OFF_BLO + off) = lo;
        }
    }
    __syncthreads();

    const int nIt = K >> 5;
    for (int it = 0; it < nIt; ++it) {
        const int cur = it & 1;

        if (it + 1 < nIt) {
#pragma unroll
            for (int p = 0; p < AP; p++)
                ra[p] = __ldg((const float4*)(aP + (it + 1) * 32 + (size_t)p * 32 * K));
#pragma unroll
            for (int p = 0; p < 4; p++)
                rb[p] = __ldg((const float4*)(bP + (it + 1) * 32 + (size_t)p * 32 * K));
        }

        const uint32_t stage = smb + cur * STAGE;
        const uint32_t aHiB = stage
            + (uint32_t)((wr * (BM/2) + (lane & 15)) * LDB + (lane >> 4) * 16);
        const uint32_t bHiB = stage + OFF_BHI + (uint32_t)((wc * 32 + lane) * LDB);

#pragma unroll
        for (int kc = 0; kc < 2; kc++) {
            uint32_t ahi[MT][4], alo[MT][4];
            uint32_t bh0[4], bh1[4], bl0[4], bl1[4];
#pragma unroll
            for (int mt = 0; mt < MT; mt++) {
                ldmx4(ahi[mt], aHiB + mt * 16 * LDB + kc * 32);
                ldmx4(alo[mt], aHiB + OFF_ALO + mt * 16 * LDB + kc * 32);
            }
            ldmx4(bh0, bHiB + kc * 32);
            ldmx4(bh1, bHiB + kc * 32 + 16);
            ldmx4(bl0, bHiB + (OFF_BLO - OFF_BHI) + kc * 32);
            ldmx4(bl1, bHiB + (OFF_BLO - OFF_BHI) + kc * 32 + 16);

#pragma unroll
            for (int mt = 0; mt < MT; mt++)
#pragma unroll
                for (int nt = 0; nt < 4; nt++) {
                    mma16816(acc[mt][nt], ahi[mt], bh0[nt], bh1[nt]);
                    mma16816(acc[mt][nt], ahi[mt], bl0[nt], bl1[nt]);
                    mma16816(acc[mt][nt], alo[mt], bh0[nt], bh1[nt]);
                }
        }

        if (it + 1 < nIt) {
            char* sp = sm + ((it + 1) & 1) * STAGE;
#pragma unroll
            for (int p = 0; p < AP; p++) {
                uint32_t off = (uint32_t)((srow + p * 32) * LDB + sc4 * 8);
                uint2 hi, lo;
                split_f4(ra[p], hi, lo);
                *(uint2*)(sp + off) = hi;
                *(uint2*)(sp + OFF_ALO + off) = lo;
            }
#pragma unroll
            for (int p = 0; p < 4; p++) {
                uint32_t off = (uint32_t)((srow + p * 32) * LDB + sc4 * 8);
                uint2 hi, lo;
                split_f4(rb[p], hi, lo);
                *(uint2*)(sp + OFF_BHI + off) = hi;
                *(uint2*)(sp + OFF_BLO + off) = lo;
            }
        }
        __syncthreads();
    }

    // ---- epilogue ----
    const int er = m0 + wr * (BM/2) + (lane >> 2);
    const int ec = n0 + wc * 32 + (lane & 3) * 2;
#pragma unroll
    for (int mt = 0; mt < MT; mt++) {
#pragma unroll
        for (int half = 0; half < 2; half++) {
            const int row = er + mt * 16 + half * 8;
            const size_t rb2 = (size_t)row * N;
            const float* rrow = res ? res + rb2 : nullptr;
#pragma unroll
            for (int nt = 0; nt < 4; nt++) {
                const int col = ec + nt * 8;
                float v0 = acc[mt][nt][half * 2 + 0];
                float v1 = acc[mt][nt][half * 2 + 1];
                if (bias) { v0 += bias[col]; v1 += bias[col + 1]; }
                if (gelu) { v0 = gelu_exact(v0); v1 = gelu_exact(v1); }
                if (rrow) { v0 += rrow[col]; v1 += rrow[col + 1]; }
                if (Cf) *(float2*)(Cf + rb2 + col) = make_float2(v0, v1);
                if (Chi) {
                    __nv_bfloat16 h0, l0, h1, l1;
                    split1(v0, h0, l0);
                    split1(v1, h1, l1);
                    *(__nv_bfloat162*)(Chi + rb2 + col) = __nv_bfloat162(h0, h1);
                    *(__nv_bfloat162*)(Clo + rb2 + col) = __nv_bfloat162(l0, l1);
                }
            }
        }
    }
}

// ---------------------------------------------------------------------------
// Batched transposes
// ---------------------------------------------------------------------------
__global__ void tr_qkv3(const float* __restrict__ Wq, const float* __restrict__ Wk,
                        const float* __restrict__ Wv, float* __restrict__ dst,
                        int l0)
{
    __shared__ float t[32][33];
    const int z = blockIdx.z;
    const int l = l0 + z / 3;
    const int which = z % 3;
    const float* src = (which == 0 ? Wq : which == 1 ? Wk : Wv)
                     + (size_t)l * DDIM * DDIM;
    float* d = dst + (size_t)l * NQKV * DDIM + (size_t)which * DDIM * DDIM;
    const int k0 = blockIdx.y * 32, n0 = blockIdx.x * 32;
    const int tx = threadIdx.x, ty = threadIdx.y;
#pragma unroll
    for (int i = 0; i < 32; i += 8)
        t[ty + i][tx] = src[(size_t)(k0 + ty + i) * DDIM + n0 + tx];
    __syncthreads();
#pragma unroll
    for (int i = 0; i < 32; i += 8)
        d[(size_t)(n0 + ty + i) * DDIM + k0 + tx] = t[tx][ty + i];
}

__global__ void transpose_b(const float* __restrict__ src, float* __restrict__ dst,
                            int K, int N, size_t sstr, size_t dstr)
{
    __shared__ float t[32][33];
    const int l = blockIdx.z;
    src += (size_t)l * sstr;
    dst += (size_t)l * dstr;
    const int k0 = blockIdx.y * 32, n0 = blockIdx.x * 32;
    const int tx = threadIdx.x, ty = threadIdx.y;
#pragma unroll
    for (int i = 0; i < 32; i += 8)
        t[ty + i][tx] = src[(size_t)(k0 + ty + i) * N + n0 + tx];
    __syncthreads();
#pragma unroll
    for (int i = 0; i < 32; i += 8)
        dst[(size_t)(n0 + ty + i) * K + k0 + tx] = t[tx][ty + i];
}

// ---------------------------------------------------------------------------
// Fused embedding + bias concat
// ---------------------------------------------------------------------------
__global__ void embed_bias(const int* __restrict__ tokens,
                           const float* __restrict__ emb,
                           const float* __restrict__ pos,
                           float* __restrict__ x,
                           const float* __restrict__ bq, const float* __restrict__ bk,
                           const float* __restrict__ bv, float* __restrict__ bqkv)
{
    if (blockIdx.x < MM) {
        int i = blockIdx.x;
        int s = i & (SSEQ - 1);
        int t = tokens[i];
        const float4* e4 = (const float4*)(emb + (size_t)t * DDIM);
        const float4* p4 = (const float4*)(pos + (size_t)s * DDIM);
        float4*       x4 = (float4*)(x + (size_t)i * DDIM);
        int d = threadIdx.x;
        float4 a = e4[d], b = p4[d];
        x4[d] = make_float4(a.x + b.x, a.y + b.y, a.z + b.z, a.w + b.w);
    } else {
        int e = (blockIdx.x - MM) * 256 + threadIdx.x;   // 0..24575
        int l = e / NQKV;
        int i = e - l * NQKV;
        float v;
        if (i < 1024)       v = bq[l * DDIM + i];
        else if (i < 2048)  v = bk[l * DDIM + i - 1024];
        else                v = bv[l * DDIM + i - 2048];
        bqkv[e] = v;
    }
}

// ---------------------------------------------------------------------------
// Tensor-core flash attention (unchanged from R6)
// ---------------------------------------------------------------------------
#define ALDB  144
#define AQHI  0
#define AQLO  18432
#define AKHI  36864
#define AARR  9216
#define ASMEM 73728

__global__ void __launch_bounds__(256, 2)
attn_mma(const __nv_bfloat16* __restrict__ qkvhi,
         const __nv_bfloat16* __restrict__ qkvlo,
         float* __restrict__ o)
{
    extern __shared__ char sm[];
    const uint32_t smb = smem_u32(sm);

    const int tid  = threadIdx.x;
    const int lane = tid & 31;
    const int w    = tid >> 5;
    const int qb   = blockIdx.x;
    const int bh   = blockIdx.y;
    const int b    = bh >> 4;
    const int h    = bh & 15;
    const int rowbase = b * SSEQ;
    const int qc = h * DKV, kc = 1024 + h * DKV, vc = 2048 + h * DKV;

    {
        const int ch  = tid & 7;
        const int wh  = (tid >> 3) & 1;
        const __nv_bfloat16* src = (wh ? qkvlo : qkvhi);
        const uint32_t dstb = smb + (wh ? AQLO : AQHI) + ch * 16;
#pragma unroll
        for (int i = 0; i < 8; i++) {
            const int r = i * 16 + (tid >> 4);
            cp16(dstb + r * ALDB,
                 src + (size_t)(rowbase + qb * 128 + r) * NQKV + qc + ch * 8);
        }
        CP_COMMIT();
    }

    float sO[8][4];
#pragma unroll
    for (int i = 0; i < 8; i++)
#pragma unroll
        for (int q = 0; q < 4; q++) sO[i][q] = 0.0f;
    float mrow[2] = { -INFINITY, -INFINITY };
    float lrow[2] = { 0.0f, 0.0f };

    const int ch  = tid & 7;
    const int arr = (tid >> 3) & 3;
    const __nv_bfloat16* kvsrc =
        (arr == 0) ? qkvhi : (arr == 1) ? qkvlo : (arr == 2) ? qkvhi : qkvlo;
    const int kvcol = (arr < 2) ? kc : vc;
    const uint32_t kvdstb = smb + AKHI + arr * AARR + ch * 16;

    const int ntile = 2 * (qb + 1);
    for (int kt = 0; kt < ntile; kt++) {
        __syncthreads();
        {
#pragma unroll
            for (int i = 0; i < 8; i++) {
                const int r = i * 8 + (tid >> 5);
                cp16(kvdstb + r * ALDB,
                     kvsrc + (size_t)(rowbase + kt * 64 + r) * NQKV + kvcol + ch * 8);
            }
            CP_COMMIT();
        }
        CP_WAIT0();
        __syncthreads();

        float s[8][4];
#pragma unroll
        for (int i = 0; i < 8; i++)
#pragma unroll
            for (int q = 0; q < 4; q++) s[i][q] = 0.0f;

        const uint32_t qHiB = smb + AQHI
            + (uint32_t)((w * 16 + (lane & 15)) * ALDB + (lane >> 4) * 16);
        const uint32_t kHiB0 = smb + AKHI + (uint32_t)(lane * ALDB);

#pragma unroll
        for (int ks = 0; ks < 4; ks++) {
            uint32_t aH[4], aL[4];
            ldmx4(aH, qHiB + ks * 32);
            ldmx4(aL, qHiB + (AQLO - AQHI) + ks * 32);
#pragma unroll
            for (int nb = 0; nb < 2; nb++) {
                const uint32_t kb = kHiB0 + nb * 32 * ALDB + ks * 32;
                uint32_t bh0[4], bh1[4], bl0[4], bl1[4];
                ldmx4(bh0, kb);
                ldmx4(bh1, kb + 16);
                ldmx4(bl0, kb + AARR);
                ldmx4(bl1, kb + AARR + 16);
#pragma unroll
                for (int nt = 0; nt < 4; nt++) {
                    float* d = s[nb * 4 + nt];
                    mma16816(d, aH, bh0[nt], bh1[nt]);
                    mma16816(d, aH, bl0[nt], bl1[nt]);
                    mma16816(d, aL, bh0[nt], bh1[nt]);
                }
            }
        }

        const int r0 = qb * 128 + w * 16 + (lane >> 2);
        const int c0 = kt * 64 + (lane & 3) * 2;
#pragma unroll
        for (int nf = 0; nf < 8; nf++) {
            const int col = c0 + nf * 8;
#pragma unroll
            for (int q = 0; q < 4; q++) {
                const int row = r0 + (q >> 1) * 8;
                const int cc  = col + (q & 1);
                float v = s[nf][q] * 0.125f;
                s[nf][q] = (cc > row) ? -INFINITY : v;
            }
        }

        float mx0 = s[0][0], mx1 = s[0][2];
#pragma unroll
        for (int nf = 0; nf < 8; nf++) {
            mx0 = fmaxf(mx0, fmaxf(s[nf][0], s[nf][1]));
            mx1 = fmaxf(mx1, fmaxf(s[nf][2], s[nf][3]));
        }
        mx0 = fmaxf(mx0, __shfl_xor_sync(0xffffffffu, mx0, 1));
        mx0 = fmaxf(mx0, __shfl_xor_sync(0xffffffffu, mx0, 2));
        mx1 = fmaxf(mx1, __shfl_xor_sync(0xffffffffu, mx1, 1));
        mx1 = fmaxf(mx1, __shfl_xor_sync(0xffffffffu, mx1, 2));

        const float mn0 = fmaxf(mrow[0], mx0);
        const float mn1 = fmaxf(mrow[1], mx1);
        const float co0 = __expf(mrow[0] - mn0);
        const float co1 = __expf(mrow[1] - mn1);
        lrow[0] *= co0; lrow[1] *= co1;
#pragma unroll
        for (int nf = 0; nf < 8; nf++) {
            sO[nf][0] *= co0; sO[nf][1] *= co0;
            sO[nf][2] *= co1; sO[nf][3] *= co1;
        }
        float su0 = 0.0f, su1 = 0.0f;
#pragma unroll
        for (int nf = 0; nf < 8; nf++) {
            s[nf][0] = __expf(s[nf][0] - mn0); su0 += s[nf][0];
            s[nf][1] = __expf(s[nf][1] - mn0); su0 += s[nf][1];
            s[nf][2] = __expf(s[nf][2] - mn1); su1 += s[nf][2];
            s[nf][3] = __expf(s[nf][3] - mn1); su1 += s[nf][3];
        }
        su0 += __shfl_xor_sync(0xffffffffu, su0, 1);
        su0 += __shfl_xor_sync(0xffffffffu, su0, 2);
        su1 += __shfl_xor_sync(0xffffffffu, su1, 1);
        su1 += __shfl_xor_sync(0xffffffffu, su1, 2);
        lrow[0] += su0; lrow[1] += su1;
        mrow[0] = mn0; mrow[1] = mn1;

        const uint32_t vHiB0 = smb + AKHI + 2 * AARR
            + (uint32_t)((lane & 15) * ALDB + (lane >> 4) * 16);
#pragma unroll
        for (int ks = 0; ks < 4; ks++) {
            uint32_t pa_h[4], pa_l[4];
            {
                __nv_bfloat16 h0, l0, h1, l1;
                split1(s[2*ks][0], h0, l0); split1(s[2*ks][1], h1, l1);
                pa_h[0] = ((uint32_t)__bfloat16_as_ushort(h1) << 16) | __bfloat16_as_ushort(h0);
                pa_l[0] = ((uint32_t)__bfloat16_as_ushort(l1) << 16) | __bfloat16_as_ushort(l0);
                split1(s[2*ks][2], h0, l0); split1(s[2*ks][3], h1, l1);
                pa_h[1] = ((uint32_t)__bfloat16_as_ushort(h1) << 16) | __bfloat16_as_ushort(h0);
                pa_l[1] = ((uint32_t)__bfloat16_as_ushort(l1) << 16) | __bfloat16_as_ushort(l0);
                split1(s[2*ks+1][0], h0, l0); split1(s[2*ks+1][1], h1, l1);
                pa_h[2] = ((uint32_t)__bfloat16_as_ushort(h1) << 16) | __bfloat16_as_ushort(h0);
                pa_l[2] = ((uint32_t)__bfloat16_as_ushort(l1) << 16) | __bfloat16_as_ushort(l0);
                split1(s[2*ks+1][2], h0, l0); split1(s[2*ks+1][3], h1, l1);
                pa_h[3] = ((uint32_t)__bfloat16_as_ushort(h1) << 16) | __bfloat16_as_ushort(h0);
                pa_l[3] = ((uint32_t)__bfloat16_as_ushort(l1) << 16) | __bfloat16_as_ushort(l0);
            }
#pragma unroll
            for (int nb = 0; nb < 4; nb++) {
                const uint32_t vb = vHiB0 + ks * 16 * ALDB + nb * 32;
                uint32_t vh[4], vl[4];
                ldmx4t(vh, vb);
                ldmx4t(vl, vb + AARR);
                float* d0 = sO[nb * 2];
                float* d1 = sO[nb * 2 + 1];
                mma16816(d0, pa_h, vh[0], vh[1]);
                mma16816(d0, pa_h, vl[0], vl[1]);
                mma16816(d0, pa_l, vh[0], vh[1]);
                mma16816(d1, pa_h, vh[2], vh[3]);
                mma16816(d1, pa_h, vl[2], vl[3]);
                mma16816(d1, pa_l, vh[2], vh[3]);
            }
        }
    }

    const float inv0 = 1.0f / lrow[0];
    const float inv1 = 1.0f / lrow[1];
    const int gr0 = rowbase + qb * 128 + w * 16 + (lane >> 2);
    const int colb = h * DKV + (lane & 3) * 2;
#pragma unroll
    for (int nf = 0; nf < 8; nf++) {
        const int col = colb + nf * 8;
        *(float2*)(o + (size_t)gr0 * DDIM + col) =
            make_float2(sO[nf][0] * inv0, sO[nf][1] * inv0);
        *(float2*)(o + (size_t)(gr0 + 8) * DDIM + col) =
            make_float2(sO[nf][2] * inv1, sO[nf][3] * inv1);
    }
}

// ---------------------------------------------------------------------------
// Host
// ---------------------------------------------------------------------------
#define GSMEM128 (2 * (2*128 + 256) * LDB)   // 81920
#define GSMEM64  (2 * (2*64  + 256) * LDB)   // 61440

static inline void run_gemm(const float* A, const float* Bt, const float* bias,
                            const float* res, float* Cf,
                            __nv_bfloat16* Chi, __nv_bfloat16* Clo,
                            int M, int N, int K, int gelu, int bm64)
{
    if (bm64) {
        dim3 grid(N / 128, M / 64);
        gemm_mma<64,2><<<grid, 256, GSMEM64>>>(A, Bt, bias, res, Cf, Chi, Clo,
                                               M, N, K, gelu);
    } else {
        dim3 grid(N / 128, M / 128);
        gemm_mma<128,1><<<grid, 256, GSMEM128>>>(A, Bt, bias, res, Cf, Chi, Clo,
                                                 M, N, K, gelu);
    }
}

extern "C" void kernel_launch(void* const* d_in, const int* in_sizes, int n_in,
                              void* d_out, int out_size)
{
    const int*   tokens = (const int*)  d_in[0];
    const float* emb    = (const float*)d_in[1];
    const float* pos    = (const float*)d_in[2];
    const float* Wq     = (const float*)d_in[3];
    const float* bq     = (const float*)d_in[4];
    const float* Wk     = (const float*)d_in[5];
    const float* bk     = (const float*)d_in[6];
    const float* Wv     = (const float*)d_in[7];
    const float* bv     = (const float*)d_in[8];
    const float* Wo     = (const float*)d_in[9];
    const float* W1     = (const float*)d_in[10];
    const float* b1     = (const float*)d_in[11];
    const float* W2     = (const float*)d_in[12];
    const float* b2     = (const float*)d_in[13];
    const float* Wr     = (const float*)d_in[14];
    const float* br     = (const float*)d_in[15];
    float*       out    = (float*)d_out;

    float *x, *o, *h, *t, *bqkv;
    __nv_bfloat16 *qkvhi, *qkvlo;
    float *WqkvT, *WoT, *W1T, *W2T, *WrT;
    cudaGetSymbolAddress((void**)&x,     g_x);
    cudaGetSymbolAddress((void**)&o,     g_o);
    cudaGetSymbolAddress((void**)&h,     g_h);
    cudaGetSymbolAddress((void**)&t,     g_t);
    cudaGetSymbolAddress((void**)&qkvhi, g_qkvhi);
    cudaGetSymbolAddress((void**)&qkvlo, g_qkvlo);
    cudaGetSymbolAddress((void**)&WqkvT, g_WqkvT);
    cudaGetSymbolAddress((void**)&WoT,   g_WoT);
    cudaGetSymbolAddress((void**)&W1T,   g_W1T);
    cudaGetSymbolAddress((void**)&W2T,   g_W2T);
    cudaGetSymbolAddress((void**)&WrT,   g_WrT);
    cudaGetSymbolAddress((void**)&bqkv,  g_bqkv);

    cudaFuncSetAttribute((const void*)gemm_mma<128,1>,
                         cudaFuncAttributeMaxDynamicSharedMemorySize, GSMEM128);
    cudaFuncSetAttribute((const void*)gemm_mma<64,2>,
                         cudaFuncAttributeMaxDynamicSharedMemorySize, GSMEM64);
    cudaFuncSetAttribute(attn_mma,
                         cudaFuncAttributeMaxDynamicSharedMemorySize, ASMEM);

    const size_t DD2 = (size_t)DDIM * DDIM;

    // launch 0: layer-0 QKV weight transpose (batched z=3)
    tr_qkv3<<<dim3(32, 32, 3), dim3(32, 8)>>>(Wq, Wk, Wv, WqkvT, 0);
    // launch 1: Wo transpose, all layers
    transpose_b<<<dim3(32, 32, LLAY), dim3(32, 8)>>>(Wo, WoT, DDIM, DDIM, DD2, DD2);
    // launch 2: embed + bias concat
    embed_bias<<<MM + 96, 256>>>(tokens, emb, pos, x, bq, bk, bv, bqkv);
    // launch 3: layer-0 QKV GEMM
    run_gemm(x, WqkvT, bqkv, nullptr, nullptr, qkvhi, qkvlo, MM, NQKV, DDIM, 0, 0);
    // launch 4: layer-0 attention
    attn_mma<<<dim3(SSEQ/128, BB*HHH), 256, ASMEM>>>(qkvhi, qkvlo, o);
    // launch 5: layer-0 Wo GEMM (BM=64)
    run_gemm(o, WoT, nullptr, x, h, nullptr, nullptr, MM, DDIM, DDIM, 0, 1);

    // remaining weight prep
    tr_qkv3<<<dim3(32, 32, 21), dim3(32, 8)>>>(Wq, Wk, Wv, WqkvT, 1);
    transpose_b<<<dim3(128, 32, LLAY), dim3(32, 8)>>>(W1, W1T, DDIM, DHH,
                                                      (size_t)DDIM*DHH, (size_t)DHH*DDIM);
    transpose_b<<<dim3(32, 128, LLAY), dim3(32, 8)>>>(W2, W2T, DHH, DDIM,
                                                      (size_t)DHH*DDIM, (size_t)DDIM*DHH);
    transpose_b<<<dim3(8, 32, 1), dim3(32, 8)>>>(Wr, WrT, DDIM, VVOC, 0, 0);

    // layer-0 MLP
    run_gemm(h, W1T, b1, nullptr, t, nullptr, nullptr, MM, DHH, DDIM, 1, 0);
    run_gemm(t, W2T, b2, h, x, nullptr, nullptr, MM, DDIM, DHH, 0, 1);

    for (int l = 1; l < LLAY; l++) {
        const float* woT = WoT + (size_t)l*DD2;
        const float* w1T = W1T + (size_t)l*DHH*DDIM;
        const float* w2T = W2T + (size_t)l*DDIM*DHH;

        run_gemm(x, WqkvT + (size_t)l*NQKV*DDIM, bqkv + (size_t)l*NQKV, nullptr,
                 nullptr, qkvhi, qkvlo, MM, NQKV, DDIM, 0, 0);
        attn_mma<<<dim3(SSEQ/128, BB*HHH), 256, ASMEM>>>(qkvhi, qkvlo, o);
        run_gemm(o, woT, nullptr, x, h, nullptr, nullptr, MM, DDIM, DDIM, 0, 1);
        run_gemm(h, w1T, b1 + (size_t)l*DHH, nullptr, t, nullptr, nullptr,
                 MM, DHH, DDIM, 1, 0);
        run_gemm(t, w2T, b2 + (size_t)l*DDIM, h, x, nullptr, nullptr,
                 MM, DDIM, DHH, 0, 1);
    }

    // LM head (BM=64)
    run_gemm(x, WrT, br, nullptr, out, nullptr, nullptr, MM, VVOC, DDIM, 0, 1);
}